// round 4
// baseline (speedup 1.0000x reference)
#include <cuda_runtime.h>

// ---------------------------------------------------------------------------
// VQ (vector-quantization) forward:
//   f = x @ W^T + b                       [N, 256]
//   idx = argmin_k ||f - e_k||^2          [N]     (K = 1024 codes)
//   quantized_st = x + (e[idx] - x)       [N, 256]
//   loss = 0.25 * mean((e[idx] - x)^2)
//   perplexity = exp(-sum p log(p+1e-10)), p = histogram(idx)/N
//   encodings = one_hot(idx, K) f32       [N, K]
//
// Output layout (flattened tuple): [loss(1) | quantized(N*256) | perp(1) | enc(N*K)]
// ---------------------------------------------------------------------------

#define NTOK   (64 * 2048)         // 131072
#define DDIM   256
#define KCODE  1024
#define QOFF   1
#define PERPOFF (1 + NTOK * DDIM)  // 33554433
#define ENCOFF  (PERPOFF + 1)      // 33554434

// scratch (static device globals: no runtime allocation)
__device__ float  g_enorm[KCODE];
__device__ int    g_idx[NTOK];
__device__ int    g_cnt[KCODE];
__device__ double g_loss;

typedef unsigned long long u64;

// ---- packed f32x2 helpers (Blackwell FFMA2: 2x fp32 FMA throughput) -------
__device__ __forceinline__ u64 pk2(float lo, float hi) {
    u64 r; asm("mov.b64 %0, {%1,%2};" : "=l"(r) : "f"(lo), "f"(hi)); return r;
}
__device__ __forceinline__ u64 ffma2(u64 a, u64 b, u64 c) {
    u64 d; asm("fma.rn.f32x2 %0, %1, %2, %3;" : "=l"(d) : "l"(a), "l"(b), "l"(c)); return d;
}
__device__ __forceinline__ float2 upk2(u64 v) {
    float lo, hi; asm("mov.b64 {%0,%1}, %2;" : "=f"(lo), "=f"(hi) : "l"(v));
    return make_float2(lo, hi);
}

// ---- shared-memory layout for the fused kernel ----------------------------
#define SPITCH       132                       // padded pitch (floats) to dodge bank conflicts
#define FS_FLOATS    (256 * SPITCH)            // resident f tile, stored [k][m]
#define STAGE_FLOATS (16 * SPITCH)             // one 128x16 stage tile, stored [k][row]
#define SMEM_FLOATS  (FS_FLOATS + 2 * STAGE_FLOATS + 128)
#define SMEM_BYTES   (SMEM_FLOATS * 4)

// Load a 128-row x 16-col tile (row stride DDIM) into registers: 2x float4/thread.
__device__ __forceinline__ void ldg_tile(const float* __restrict__ src, int tid,
                                         float4& v0, float4& v1) {
    int r0 = tid >> 2, c0 = (tid & 3) << 2;
    v0 = *reinterpret_cast<const float4*>(src + r0 * DDIM + c0);
    int id1 = tid + 256;
    int r1 = id1 >> 2, c1 = (id1 & 3) << 2;
    v1 = *reinterpret_cast<const float4*>(src + r1 * DDIM + c1);
}
// Store those registers transposed into smem stage tile S[k][row] (pitch SPITCH).
__device__ __forceinline__ void sts_tile(float* S, int tid,
                                         const float4& v0, const float4& v1) {
    int r0 = tid >> 2, c0 = (tid & 3) << 2;
    S[(c0 + 0) * SPITCH + r0] = v0.x;
    S[(c0 + 1) * SPITCH + r0] = v0.y;
    S[(c0 + 2) * SPITCH + r0] = v0.z;
    S[(c0 + 3) * SPITCH + r0] = v0.w;
    int id1 = tid + 256;
    int r1 = id1 >> 2, c1 = (id1 & 3) << 2;
    S[(c1 + 0) * SPITCH + r1] = v1.x;
    S[(c1 + 1) * SPITCH + r1] = v1.y;
    S[(c1 + 2) * SPITCH + r1] = v1.z;
    S[(c1 + 3) * SPITCH + r1] = v1.w;
}

// One k-step of the 8x8 micro-tile (packed over column pairs): 32 FFMA2 = 64 FMA.
__device__ __forceinline__ void mm_step(const float* __restrict__ a_row,
                                        const float* __restrict__ b_row,
                                        int ty8, int tx8, u64* acc) {
    float4 aA = *reinterpret_cast<const float4*>(a_row + ty8);
    float4 aB = *reinterpret_cast<const float4*>(a_row + ty8 + 4);
    float4 bA = *reinterpret_cast<const float4*>(b_row + tx8);
    float4 bB = *reinterpret_cast<const float4*>(b_row + tx8 + 4);
    u64 b2[4];
    b2[0] = pk2(bA.x, bA.y); b2[1] = pk2(bA.z, bA.w);
    b2[2] = pk2(bB.x, bB.y); b2[3] = pk2(bB.z, bB.w);
    float av[8] = {aA.x, aA.y, aA.z, aA.w, aB.x, aB.y, aB.z, aB.w};
#pragma unroll
    for (int i = 0; i < 8; i++) {
        u64 aa = pk2(av[i], av[i]);
#pragma unroll
        for (int j = 0; j < 4; j++) acc[i * 4 + j] = ffma2(aa, b2[j], acc[i * 4 + j]);
    }
}

// ---------------------------------------------------------------------------
// Fused kernel: per CTA of 128 tokens:
//   phase 1: f tile = x @ W^T + b  (resident in smem, transposed [k][m])
//   phase 2: distances vs all 1024 codes, argmin with first-index tie-break,
//            histogram atomics.
// ---------------------------------------------------------------------------
__global__ void __launch_bounds__(256, 1)
vq_main(const float* __restrict__ x, const float* __restrict__ W,
        const float* __restrict__ bias, const float* __restrict__ E) {
    extern __shared__ float sm[];
    float* f_s  = sm;                          // [256][SPITCH]
    float* As   = sm + FS_FLOATS;              // [16][SPITCH]
    float* Bs   = As + STAGE_FLOATS;           // [16][SPITCH]
    float* f2_s = Bs + STAGE_FLOATS;           // [128]

    const int tid = threadIdx.x;
    const int tx = tid & 15, ty = tid >> 4;
    const int tx8 = tx * 8, ty8 = ty * 8;
    const int row0 = blockIdx.x * 128;
    const float* xbase = x + (size_t)row0 * DDIM;

    // ---------------- phase 1: pre-linear ----------------
#pragma unroll 1
    for (int jt = 0; jt < 2; jt++) {
        u64 acc[32];
#pragma unroll
        for (int i = 0; i < 32; i++) acc[i] = 0ull;
        const float* wsrc = W + (size_t)jt * 128 * DDIM;
        float4 a0, a1, b0, b1;
        ldg_tile(xbase, tid, a0, a1);
        ldg_tile(wsrc, tid, b0, b1);
#pragma unroll 1
        for (int s = 0; s < 16; s++) {
            __syncthreads();
            sts_tile(As, tid, a0, a1);
            sts_tile(Bs, tid, b0, b1);
            if (s < 15) {
                ldg_tile(xbase + (s + 1) * 16, tid, a0, a1);
                ldg_tile(wsrc + (s + 1) * 16, tid, b0, b1);
            }
            __syncthreads();
#pragma unroll
            for (int kk = 0; kk < 16; kk++)
                mm_step(As + kk * SPITCH, Bs + kk * SPITCH, ty8, tx8, acc);
        }
        // epilogue: f_s[col][row] = acc + bias
        float4 bb0 = *reinterpret_cast<const float4*>(bias + jt * 128 + tx8);
        float4 bb1 = *reinterpret_cast<const float4*>(bias + jt * 128 + tx8 + 4);
        float bv[8] = {bb0.x, bb0.y, bb0.z, bb0.w, bb1.x, bb1.y, bb1.z, bb1.w};
#pragma unroll
        for (int i = 0; i < 8; i++) {
            int row = ty8 + i;
#pragma unroll
            for (int jp = 0; jp < 4; jp++) {
                float2 v = upk2(acc[i * 4 + jp]);
                int c = jt * 128 + tx8 + jp * 2;
                f_s[(c + 0) * SPITCH + row] = v.x + bv[jp * 2 + 0];
                f_s[(c + 1) * SPITCH + row] = v.y + bv[jp * 2 + 1];
            }
        }
    }
    __syncthreads();

    // per-token ||f||^2
    if (tid < 128) {
        float s = 0.0f;
        for (int k = 0; k < 256; k++) {
            float v = f_s[k * SPITCH + tid];
            s = __fmaf_rn(v, v, s);
        }
        f2_s[tid] = s;
    }
    __syncthreads();

    // ---------------- phase 2: distances + argmin ----------------
    float bestv[8];
    int besti[8];
#pragma unroll
    for (int i = 0; i < 8; i++) { bestv[i] = 3.4e38f; besti[i] = 0; }

#pragma unroll 1
    for (int nt = 0; nt < 8; nt++) {
        u64 acc[32];
#pragma unroll
        for (int i = 0; i < 32; i++) acc[i] = 0ull;
        const float* esrc = E + (size_t)nt * 128 * DDIM;
        float4 b0, b1;
        ldg_tile(esrc, tid, b0, b1);
#pragma unroll 1
        for (int s = 0; s < 16; s++) {
            __syncthreads();
            sts_tile(Bs, tid, b0, b1);
            if (s < 15) ldg_tile(esrc + (s + 1) * 16, tid, b0, b1);
            __syncthreads();
#pragma unroll
            for (int kk = 0; kk < 16; kk++)
                mm_step(f_s + (s * 16 + kk) * SPITCH, Bs + kk * SPITCH, ty8, tx8, acc);
        }
        // epilogue: d = (||f||^2 + ||e||^2) - 2*dot  (match reference rounding)
        float4 e0 = *reinterpret_cast<const float4*>(g_enorm + nt * 128 + tx8);
        float4 e1 = *reinterpret_cast<const float4*>(g_enorm + nt * 128 + tx8 + 4);
        float en[8] = {e0.x, e0.y, e0.z, e0.w, e1.x, e1.y, e1.z, e1.w};
#pragma unroll
        for (int i = 0; i < 8; i++) {
            float f2 = f2_s[ty8 + i];
#pragma unroll
            for (int jp = 0; jp < 4; jp++) {
                float2 v = upk2(acc[i * 4 + jp]);
                int c = nt * 128 + tx8 + jp * 2;
                float d0 = __fsub_rn(__fadd_rn(f2, en[jp * 2 + 0]), __fmul_rn(2.0f, v.x));
                float d1 = __fsub_rn(__fadd_rn(f2, en[jp * 2 + 1]), __fmul_rn(2.0f, v.y));
                if (d0 < bestv[i]) { bestv[i] = d0; besti[i] = c; }
                if (d1 < bestv[i]) { bestv[i] = d1; besti[i] = c + 1; }
            }
        }
    }

    // reduce across the 16 tx threads holding the same 8 tokens (within warp half)
#pragma unroll
    for (int i = 0; i < 8; i++) {
        float v = bestv[i];
        int ix = besti[i];
#pragma unroll
        for (int o = 8; o; o >>= 1) {
            float ov = __shfl_xor_sync(0xffffffffu, v, o);
            int   oi = __shfl_xor_sync(0xffffffffu, ix, o);
            if (ov < v || (ov == v && oi < ix)) { v = ov; ix = oi; }
        }
        if (tx == 0) {
            int token = row0 + ty8 + i;
            g_idx[token] = ix;
            atomicAdd(&g_cnt[ix], 1);
        }
    }
}

// ---------------------------------------------------------------------------
// Small kernels
// ---------------------------------------------------------------------------
__global__ void init_k() {
    int t = threadIdx.x;
    if (t < KCODE) g_cnt[t] = 0;
    if (t == 0) g_loss = 0.0;
}

__global__ void enorm_k(const float* __restrict__ E) {
    int k = blockIdx.x, lane = threadIdx.x;
    const float4* e4 = reinterpret_cast<const float4*>(E + (size_t)k * DDIM);
    float4 a = e4[lane * 2], b = e4[lane * 2 + 1];
    float s = a.x * a.x + a.y * a.y + a.z * a.z + a.w * a.w
            + b.x * b.x + b.y * b.y + b.z * b.z + b.w * b.w;
#pragma unroll
    for (int o = 16; o; o >>= 1) s += __shfl_xor_sync(0xffffffffu, s, o);
    if (lane == 0) g_enorm[k] = s;
}

__global__ void enc_zero(float* __restrict__ out) {
    float2* p = reinterpret_cast<float2*>(out + ENCOFF);  // even offset -> 8B aligned
    long long n = (long long)NTOK * KCODE / 2;
    long long i = (long long)blockIdx.x * blockDim.x + threadIdx.x;
    long long stride = (long long)gridDim.x * blockDim.x;
    float2 z = make_float2(0.0f, 0.0f);
    for (; i < n; i += stride) p[i] = z;
}

__global__ void enc_ones(float* __restrict__ out) {
    int n = blockIdx.x * blockDim.x + threadIdx.x;
    if (n < NTOK) out[(long long)ENCOFF + (long long)n * KCODE + g_idx[n]] = 1.0f;
}

__global__ void quant_loss(float* __restrict__ out, const float* __restrict__ x,
                           const float* __restrict__ E) {
    int warp = (blockIdx.x * blockDim.x + threadIdx.x) >> 5;
    int lane = threadIdx.x & 31;
    if (warp >= NTOK) return;
    int c = g_idx[warp];
    const float4* e4 = reinterpret_cast<const float4*>(E + (size_t)c * DDIM);
    const float4* x4 = reinterpret_cast<const float4*>(x + (size_t)warp * DDIM);
    float4 e0 = e4[lane * 2], e1 = e4[lane * 2 + 1];
    float4 v0 = x4[lane * 2], v1 = x4[lane * 2 + 1];
    float* q = out + QOFF + (size_t)warp * DDIM + lane * 8;
    float s = 0.0f, d;
    d = __fsub_rn(e0.x, v0.x); q[0] = __fadd_rn(v0.x, d); s = __fmaf_rn(d, d, s);
    d = __fsub_rn(e0.y, v0.y); q[1] = __fadd_rn(v0.y, d); s = __fmaf_rn(d, d, s);
    d = __fsub_rn(e0.z, v0.z); q[2] = __fadd_rn(v0.z, d); s = __fmaf_rn(d, d, s);
    d = __fsub_rn(e0.w, v0.w); q[3] = __fadd_rn(v0.w, d); s = __fmaf_rn(d, d, s);
    d = __fsub_rn(e1.x, v1.x); q[4] = __fadd_rn(v1.x, d); s = __fmaf_rn(d, d, s);
    d = __fsub_rn(e1.y, v1.y); q[5] = __fadd_rn(v1.y, d); s = __fmaf_rn(d, d, s);
    d = __fsub_rn(e1.z, v1.z); q[6] = __fadd_rn(v1.z, d); s = __fmaf_rn(d, d, s);
    d = __fsub_rn(e1.w, v1.w); q[7] = __fadd_rn(v1.w, d); s = __fmaf_rn(d, d, s);
#pragma unroll
    for (int o = 16; o; o >>= 1) s += __shfl_xor_sync(0xffffffffu, s, o);
    if (lane == 0) atomicAdd(&g_loss, (double)s);
}

__global__ void final_k(float* __restrict__ out) {
    __shared__ double red[32];
    int t = threadIdx.x;
    double p = (double)g_cnt[t] / (double)NTOK;
    double v = p * log(p + 1e-10);
#pragma unroll
    for (int o = 16; o; o >>= 1) v += __shfl_xor_sync(0xffffffffu, v, o);
    if ((t & 31) == 0) red[t >> 5] = v;
    __syncthreads();
    if (t < 32) {
        double w = red[t];
#pragma unroll
        for (int o = 16; o; o >>= 1) w += __shfl_xor_sync(0xffffffffu, w, o);
        if (t == 0) {
            out[PERPOFF] = (float)exp(-w);
            out[0] = (float)(0.25 * g_loss / (double)((long long)NTOK * DDIM));
        }
    }
}

// ---------------------------------------------------------------------------
extern "C" void kernel_launch(void* const* d_in, const int* in_sizes, int n_in,
                              void* d_out, int out_size) {
    const float* x = (const float*)d_in[0];   // inputs  [64,2048,256]
    const float* W = (const float*)d_in[1];   // pre_w   [256,256]
    const float* b = (const float*)d_in[2];   // pre_b   [256]
    const float* E = (const float*)d_in[3];   // emb     [1024,256]
    float* out = (float*)d_out;

    cudaFuncSetAttribute(vq_main, cudaFuncAttributeMaxDynamicSharedMemorySize, SMEM_BYTES);

    init_k<<<1, 1024>>>();
    enorm_k<<<KCODE, 32>>>(E);
    vq_main<<<NTOK / 128, 256, SMEM_BYTES>>>(x, W, b, E);
    enc_zero<<<8192, 256>>>(out);
    enc_ones<<<NTOK / 256, 256>>>(out);
    quant_loss<<<NTOK / 8, 256>>>(out, x, E);
    final_k<<<1, 1024>>>(out);
}

// round 5
// speedup vs baseline: 1.0007x; 1.0007x over previous
#include <cuda_runtime.h>

// ---------------------------------------------------------------------------
// VQ (vector-quantization) forward:
//   f = x @ W^T + b                       [N, 256]
//   idx = argmin_k ||f - e_k||^2          [N]     (K = 1024 codes)
//   quantized_st = x + (e[idx] - x)       [N, 256]
//   loss = 0.25 * mean((e[idx] - x)^2)
//   perplexity = exp(-sum p log(p+1e-10)), p = histogram(idx)/N
//   encodings = one_hot(idx, K) f32       [N, K]
//
// Output layout (flattened tuple): [loss(1) | quantized(N*256) | perp(1) | enc(N*K)]
// ---------------------------------------------------------------------------

#define NTOK   (64 * 2048)         // 131072
#define DDIM   256
#define KCODE  1024
#define QOFF   1
#define PERPOFF (1 + NTOK * DDIM)  // 33554433
#define ENCOFF  (PERPOFF + 1)      // 33554434

// scratch (static device globals: no runtime allocation)
__device__ float  g_enorm[KCODE];
__device__ int    g_idx[NTOK];
__device__ int    g_cnt[KCODE];
__device__ double g_loss;

typedef unsigned long long u64;

// ---- packed f32x2 helpers (Blackwell FFMA2: 2x fp32 FMA throughput) -------
__device__ __forceinline__ u64 pk2(float lo, float hi) {
    u64 r; asm("mov.b64 %0, {%1,%2};" : "=l"(r) : "f"(lo), "f"(hi)); return r;
}
__device__ __forceinline__ u64 ffma2(u64 a, u64 b, u64 c) {
    u64 d; asm("fma.rn.f32x2 %0, %1, %2, %3;" : "=l"(d) : "l"(a), "l"(b), "l"(c)); return d;
}
__device__ __forceinline__ float2 upk2(u64 v) {
    float lo, hi; asm("mov.b64 {%0,%1}, %2;" : "=f"(lo), "=f"(hi) : "l"(v));
    return make_float2(lo, hi);
}

// ---- shared-memory layout for the fused kernel ----------------------------
#define SPITCH       132                       // padded pitch (floats) to dodge bank conflicts
#define FS_FLOATS    (256 * SPITCH)            // resident f tile, stored [k][m]
#define STAGE_FLOATS (16 * SPITCH)             // one 128x16 stage tile, stored [k][row]
#define SMEM_FLOATS  (FS_FLOATS + 2 * STAGE_FLOATS + 128)
#define SMEM_BYTES   (SMEM_FLOATS * 4)

// Load a 128-row x 16-col tile (row stride DDIM) into registers: 2x float4/thread.
__device__ __forceinline__ void ldg_tile(const float* __restrict__ src, int tid,
                                         float4& v0, float4& v1) {
    int r0 = tid >> 2, c0 = (tid & 3) << 2;
    v0 = *reinterpret_cast<const float4*>(src + r0 * DDIM + c0);
    int id1 = tid + 256;
    int r1 = id1 >> 2, c1 = (id1 & 3) << 2;
    v1 = *reinterpret_cast<const float4*>(src + r1 * DDIM + c1);
}
// Store those registers transposed into smem stage tile S[k][row] (pitch SPITCH).
__device__ __forceinline__ void sts_tile(float* S, int tid,
                                         const float4& v0, const float4& v1) {
    int r0 = tid >> 2, c0 = (tid & 3) << 2;
    S[(c0 + 0) * SPITCH + r0] = v0.x;
    S[(c0 + 1) * SPITCH + r0] = v0.y;
    S[(c0 + 2) * SPITCH + r0] = v0.z;
    S[(c0 + 3) * SPITCH + r0] = v0.w;
    int id1 = tid + 256;
    int r1 = id1 >> 2, c1 = (id1 & 3) << 2;
    S[(c1 + 0) * SPITCH + r1] = v1.x;
    S[(c1 + 1) * SPITCH + r1] = v1.y;
    S[(c1 + 2) * SPITCH + r1] = v1.z;
    S[(c1 + 3) * SPITCH + r1] = v1.w;
}

// One k-step of the 8x8 micro-tile (packed over column pairs): 32 FFMA2 = 64 FMA.
__device__ __forceinline__ void mm_step(const float* __restrict__ a_row,
                                        const float* __restrict__ b_row,
                                        int ty8, int tx8, u64* acc) {
    float4 aA = *reinterpret_cast<const float4*>(a_row + ty8);
    float4 aB = *reinterpret_cast<const float4*>(a_row + ty8 + 4);
    float4 bA = *reinterpret_cast<const float4*>(b_row + tx8);
    float4 bB = *reinterpret_cast<const float4*>(b_row + tx8 + 4);
    u64 b2[4];
    b2[0] = pk2(bA.x, bA.y); b2[1] = pk2(bA.z, bA.w);
    b2[2] = pk2(bB.x, bB.y); b2[3] = pk2(bB.z, bB.w);
    float av[8] = {aA.x, aA.y, aA.z, aA.w, aB.x, aB.y, aB.z, aB.w};
#pragma unroll
    for (int i = 0; i < 8; i++) {
        u64 aa = pk2(av[i], av[i]);
#pragma unroll
        for (int j = 0; j < 4; j++) acc[i * 4 + j] = ffma2(aa, b2[j], acc[i * 4 + j]);
    }
}

// ---------------------------------------------------------------------------
// Fused kernel: per CTA of 128 tokens:
//   phase 1: f tile = x @ W^T + b  (resident in smem, transposed [k][m])
//   phase 2: distances vs all 1024 codes, argmin with first-index tie-break,
//            histogram atomics.
// ---------------------------------------------------------------------------
__global__ void __launch_bounds__(256, 1)
vq_main(const float* __restrict__ x, const float* __restrict__ W,
        const float* __restrict__ bias, const float* __restrict__ E) {
    extern __shared__ float sm[];
    float* f_s  = sm;                          // [256][SPITCH]
    float* As   = sm + FS_FLOATS;              // [16][SPITCH]
    float* Bs   = As + STAGE_FLOATS;           // [16][SPITCH]
    float* f2_s = Bs + STAGE_FLOATS;           // [128]

    const int tid = threadIdx.x;
    const int tx = tid & 15, ty = tid >> 4;
    const int tx8 = tx * 8, ty8 = ty * 8;
    const int row0 = blockIdx.x * 128;
    const float* xbase = x + (size_t)row0 * DDIM;

    // ---------------- phase 1: pre-linear ----------------
#pragma unroll 1
    for (int jt = 0; jt < 2; jt++) {
        u64 acc[32];
#pragma unroll
        for (int i = 0; i < 32; i++) acc[i] = 0ull;
        const float* wsrc = W + (size_t)jt * 128 * DDIM;
        float4 a0, a1, b0, b1;
        ldg_tile(xbase, tid, a0, a1);
        ldg_tile(wsrc, tid, b0, b1);
#pragma unroll 1
        for (int s = 0; s < 16; s++) {
            __syncthreads();
            sts_tile(As, tid, a0, a1);
            sts_tile(Bs, tid, b0, b1);
            if (s < 15) {
                ldg_tile(xbase + (s + 1) * 16, tid, a0, a1);
                ldg_tile(wsrc + (s + 1) * 16, tid, b0, b1);
            }
            __syncthreads();
#pragma unroll
            for (int kk = 0; kk < 16; kk++)
                mm_step(As + kk * SPITCH, Bs + kk * SPITCH, ty8, tx8, acc);
        }
        // epilogue: f_s[col][row] = acc + bias
        float4 bb0 = *reinterpret_cast<const float4*>(bias + jt * 128 + tx8);
        float4 bb1 = *reinterpret_cast<const float4*>(bias + jt * 128 + tx8 + 4);
        float bv[8] = {bb0.x, bb0.y, bb0.z, bb0.w, bb1.x, bb1.y, bb1.z, bb1.w};
#pragma unroll
        for (int i = 0; i < 8; i++) {
            int row = ty8 + i;
#pragma unroll
            for (int jp = 0; jp < 4; jp++) {
                float2 v = upk2(acc[i * 4 + jp]);
                int c = jt * 128 + tx8 + jp * 2;
                f_s[(c + 0) * SPITCH + row] = v.x + bv[jp * 2 + 0];
                f_s[(c + 1) * SPITCH + row] = v.y + bv[jp * 2 + 1];
            }
        }
    }
    __syncthreads();

    // per-token ||f||^2
    if (tid < 128) {
        float s = 0.0f;
        for (int k = 0; k < 256; k++) {
            float v = f_s[k * SPITCH + tid];
            s = __fmaf_rn(v, v, s);
        }
        f2_s[tid] = s;
    }
    __syncthreads();

    // ---------------- phase 2: distances + argmin ----------------
    float bestv[8];
    int besti[8];
#pragma unroll
    for (int i = 0; i < 8; i++) { bestv[i] = 3.4e38f; besti[i] = 0; }

#pragma unroll 1
    for (int nt = 0; nt < 8; nt++) {
        u64 acc[32];
#pragma unroll
        for (int i = 0; i < 32; i++) acc[i] = 0ull;
        const float* esrc = E + (size_t)nt * 128 * DDIM;
        float4 b0, b1;
        ldg_tile(esrc, tid, b0, b1);
#pragma unroll 1
        for (int s = 0; s < 16; s++) {
            __syncthreads();
            sts_tile(Bs, tid, b0, b1);
            if (s < 15) ldg_tile(esrc + (s + 1) * 16, tid, b0, b1);
            __syncthreads();
#pragma unroll
            for (int kk = 0; kk < 16; kk++)
                mm_step(f_s + (s * 16 + kk) * SPITCH, Bs + kk * SPITCH, ty8, tx8, acc);
        }
        // epilogue: d = (||f||^2 + ||e||^2) - 2*dot  (match reference rounding)
        float4 e0 = *reinterpret_cast<const float4*>(g_enorm + nt * 128 + tx8);
        float4 e1 = *reinterpret_cast<const float4*>(g_enorm + nt * 128 + tx8 + 4);
        float en[8] = {e0.x, e0.y, e0.z, e0.w, e1.x, e1.y, e1.z, e1.w};
#pragma unroll
        for (int i = 0; i < 8; i++) {
            float f2 = f2_s[ty8 + i];
#pragma unroll
            for (int jp = 0; jp < 4; jp++) {
                float2 v = upk2(acc[i * 4 + jp]);
                int c = nt * 128 + tx8 + jp * 2;
                float d0 = __fsub_rn(__fadd_rn(f2, en[jp * 2 + 0]), __fmul_rn(2.0f, v.x));
                float d1 = __fsub_rn(__fadd_rn(f2, en[jp * 2 + 1]), __fmul_rn(2.0f, v.y));
                if (d0 < bestv[i]) { bestv[i] = d0; besti[i] = c; }
                if (d1 < bestv[i]) { bestv[i] = d1; besti[i] = c + 1; }
            }
        }
    }

    // reduce across the 16 tx threads holding the same 8 tokens (within warp half)
#pragma unroll
    for (int i = 0; i < 8; i++) {
        float v = bestv[i];
        int ix = besti[i];
#pragma unroll
        for (int o = 8; o; o >>= 1) {
            float ov = __shfl_xor_sync(0xffffffffu, v, o);
            int   oi = __shfl_xor_sync(0xffffffffu, ix, o);
            if (ov < v || (ov == v && oi < ix)) { v = ov; ix = oi; }
        }
        if (tx == 0) {
            int token = row0 + ty8 + i;
            g_idx[token] = ix;
            atomicAdd(&g_cnt[ix], 1);
        }
    }
}

// ---------------------------------------------------------------------------
// Small kernels
// ---------------------------------------------------------------------------
__global__ void init_k() {
    int t = threadIdx.x;
    if (t < KCODE) g_cnt[t] = 0;
    if (t == 0) g_loss = 0.0;
}

__global__ void enorm_k(const float* __restrict__ E) {
    int k = blockIdx.x, lane = threadIdx.x;
    const float4* e4 = reinterpret_cast<const float4*>(E + (size_t)k * DDIM);
    float4 a = e4[lane * 2], b = e4[lane * 2 + 1];
    float s = a.x * a.x + a.y * a.y + a.z * a.z + a.w * a.w
            + b.x * b.x + b.y * b.y + b.z * b.z + b.w * b.w;
#pragma unroll
    for (int o = 16; o; o >>= 1) s += __shfl_xor_sync(0xffffffffu, s, o);
    if (lane == 0) g_enorm[k] = s;
}

__global__ void enc_zero(float* __restrict__ out) {
    float2* p = reinterpret_cast<float2*>(out + ENCOFF);  // even offset -> 8B aligned
    long long n = (long long)NTOK * KCODE / 2;
    long long i = (long long)blockIdx.x * blockDim.x + threadIdx.x;
    long long stride = (long long)gridDim.x * blockDim.x;
    float2 z = make_float2(0.0f, 0.0f);
    for (; i < n; i += stride) p[i] = z;
}

__global__ void enc_ones(float* __restrict__ out) {
    int n = blockIdx.x * blockDim.x + threadIdx.x;
    if (n < NTOK) out[(long long)ENCOFF + (long long)n * KCODE + g_idx[n]] = 1.0f;
}

__global__ void quant_loss(float* __restrict__ out, const float* __restrict__ x,
                           const float* __restrict__ E) {
    int warp = (blockIdx.x * blockDim.x + threadIdx.x) >> 5;
    int lane = threadIdx.x & 31;
    if (warp >= NTOK) return;
    int c = g_idx[warp];
    const float4* e4 = reinterpret_cast<const float4*>(E + (size_t)c * DDIM);
    const float4* x4 = reinterpret_cast<const float4*>(x + (size_t)warp * DDIM);
    float4 e0 = e4[lane * 2], e1 = e4[lane * 2 + 1];
    float4 v0 = x4[lane * 2], v1 = x4[lane * 2 + 1];
    float* q = out + QOFF + (size_t)warp * DDIM + lane * 8;
    float s = 0.0f, d;
    d = __fsub_rn(e0.x, v0.x); q[0] = __fadd_rn(v0.x, d); s = __fmaf_rn(d, d, s);
    d = __fsub_rn(e0.y, v0.y); q[1] = __fadd_rn(v0.y, d); s = __fmaf_rn(d, d, s);
    d = __fsub_rn(e0.z, v0.z); q[2] = __fadd_rn(v0.z, d); s = __fmaf_rn(d, d, s);
    d = __fsub_rn(e0.w, v0.w); q[3] = __fadd_rn(v0.w, d); s = __fmaf_rn(d, d, s);
    d = __fsub_rn(e1.x, v1.x); q[4] = __fadd_rn(v1.x, d); s = __fmaf_rn(d, d, s);
    d = __fsub_rn(e1.y, v1.y); q[5] = __fadd_rn(v1.y, d); s = __fmaf_rn(d, d, s);
    d = __fsub_rn(e1.z, v1.z); q[6] = __fadd_rn(v1.z, d); s = __fmaf_rn(d, d, s);
    d = __fsub_rn(e1.w, v1.w); q[7] = __fadd_rn(v1.w, d); s = __fmaf_rn(d, d, s);
#pragma unroll
    for (int o = 16; o; o >>= 1) s += __shfl_xor_sync(0xffffffffu, s, o);
    if (lane == 0) atomicAdd(&g_loss, (double)s);
}

__global__ void final_k(float* __restrict__ out) {
    __shared__ double red[32];
    int t = threadIdx.x;
    double p = (double)g_cnt[t] / (double)NTOK;
    double v = p * log(p + 1e-10);
#pragma unroll
    for (int o = 16; o; o >>= 1) v += __shfl_xor_sync(0xffffffffu, v, o);
    if ((t & 31) == 0) red[t >> 5] = v;
    __syncthreads();
    if (t < 32) {
        double w = red[t];
#pragma unroll
        for (int o = 16; o; o >>= 1) w += __shfl_xor_sync(0xffffffffu, w, o);
        if (t == 0) {
            out[PERPOFF] = (float)exp(-w);
            out[0] = (float)(0.25 * g_loss / (double)((long long)NTOK * DDIM));
        }
    }
}

// ---------------------------------------------------------------------------
extern "C" void kernel_launch(void* const* d_in, const int* in_sizes, int n_in,
                              void* d_out, int out_size) {
    const float* x = (const float*)d_in[0];   // inputs  [64,2048,256]
    const float* W = (const float*)d_in[1];   // pre_w   [256,256]
    const float* b = (const float*)d_in[2];   // pre_b   [256]
    const float* E = (const float*)d_in[3];   // emb     [1024,256]
    float* out = (float*)d_out;

    cudaFuncSetAttribute(vq_main, cudaFuncAttributeMaxDynamicSharedMemorySize, SMEM_BYTES);

    init_k<<<1, 1024>>>();
    enorm_k<<<KCODE, 32>>>(E);
    vq_main<<<NTOK / 128, 256, SMEM_BYTES>>>(x, W, b, E);
    enc_zero<<<8192, 256>>>(out);
    enc_ones<<<NTOK / 256, 256>>>(out);
    quant_loss<<<NTOK / 8, 256>>>(out, x, E);
    final_k<<<1, 1024>>>(out);
}